// round 2
// baseline (speedup 1.0000x reference)
#include <cuda_runtime.h>
#include <math.h>

#define BB 32
#define CC 512
#define TT 1024
#define KS 13
#define RAD 6
#define TILE_T 32
#define NTILES (TT / TILE_T)     // 32
#define NTHR 128
#define WCH 32                   // channels per warp
#define INROWS (WCH + 2 * RAD)   // 44
#define SROW 36                  // padded row stride (floats) -> conflict-free
#define DROW 36
#define THRV 0.5f
#define BETA 0.95f

#define IN_WARP (INROWS * SROW)          // 1584 floats
#define IN_BUF  (4 * IN_WARP)            // 6336
#define DR_WARP (WCH * DROW)             // 1152
#define DR_BUF  (4 * DR_WARP)            // 4608
#define SMEM_FLOATS (2 * IN_BUF + 2 * DR_BUF)   // 21888 floats = 87552 B

typedef unsigned long long ull;

__device__ __forceinline__ void cp_async_16(unsigned saddr, const void* gptr, int src_sz) {
    asm volatile("cp.async.ca.shared.global [%0], [%1], 16, %2;\n"
                 :: "r"(saddr), "l"(gptr), "r"(src_sz));
}
__device__ __forceinline__ void cp_commit() {
    asm volatile("cp.async.commit_group;\n");
}
__device__ __forceinline__ void cp_wait1() {
    asm volatile("cp.async.wait_group 1;\n");
}
__device__ __forceinline__ void ffma2(ull& d, ull a, ull b) {
    asm("fma.rn.f32x2 %0, %1, %2, %0;" : "+l"(d) : "l"(a), "l"(b));
}
__device__ __forceinline__ ull pack2(float a) {
    ull r;
    asm("mov.b64 %0, {%1, %2};" : "=l"(r) : "f"(a), "f"(a));
    return r;
}

// Per-warp load of its 44-row (channel-halo) x 32-t tile. 352 float4 = 11 per lane.
__device__ __forceinline__ void load_warp(const float* __restrict__ xb, int chan0,
                                          int t0, float* __restrict__ buf, int lane) {
#pragma unroll
    for (int it = 0; it < 11; ++it) {
        int i = lane + 32 * it;          // 0..351
        int row = i >> 3;                // 0..43
        int gg = i & 7;
        int ch = chan0 + row - RAD;
        bool valid = ((unsigned)ch < (unsigned)CC);
        const float* gp = xb + (size_t)(valid ? ch : 0) * TT + t0 + gg * 4;
        unsigned sa = (unsigned)__cvta_generic_to_shared(buf + row * SROW + gg * 4);
        cp_async_16(sa, gp, valid ? 16 : 0);
    }
}

extern __shared__ float smem[];

__global__ void __launch_bounds__(NTHR, 1)
snn_lif2(const float* __restrict__ x,
         const float* __restrict__ wp,
         float* __restrict__ out) {
    const int tid  = threadIdx.x;
    const int w    = tid >> 5;
    const int lane = tid & 31;
    const int s    = lane >> 3;   // channel strip within warp (0..3)
    const int g    = lane & 7;    // float4 t-group (0..7)
    const int b    = blockIdx.y;
    const int chan0 = blockIdx.x * 128 + w * WCH;   // first channel of this warp

    const float* xb   = x + (size_t)b * CC * TT;
    float*       outb = out + (size_t)b * CC * TT + (size_t)(chan0 + lane) * TT;

    float* IN[2] = { smem + w * IN_WARP,
                     smem + IN_BUF + w * IN_WARP };
    float* DR[2] = { smem + 2 * IN_BUF + w * DR_WARP,
                     smem + 2 * IN_BUF + DR_BUF + w * DR_WARP };

    // --- modified Gaussian taps: drive = sum_j kw2[j] * x[c+j-6],
    //     kw2[j] = (j==6 ? 1 : 0) - kw[j]  (folds the center subtraction) ---
    float wv = wp[0];
    float sigma = 0.5f * (1.0f + 10.0f) + fminf(fmaxf(wv, 1.0f), 10.0f);
    float inv2s2 = 0.5f / (sigma * sigma);
    float kw[KS];
    float ksum = 0.0f;
#pragma unroll
    for (int j = 0; j < KS; ++j) {
        float r = (float)(j - RAD);
        kw[j] = expf(-r * r * inv2s2);
        ksum += kw[j];
    }
    float kinv = 1.0f / ksum;
    ull kp[KS];
#pragma unroll
    for (int j = 0; j < KS; ++j) {
        float t = -kw[j] * kinv;
        if (j == RAD) t += 1.0f;
        kp[j] = pack2(t);
    }

    // prologue: load tile 0
    load_warp(xb, chan0, 0, IN[0], lane);
    cp_commit();

    float mem = 0.0f, spk = 0.0f;

    for (int i = 0; i <= NTILES; ++i) {
        __syncwarp();
        if (i + 1 < NTILES)
            load_warp(xb, chan0, (i + 1) * TILE_T, IN[(i + 1) & 1], lane);
        cp_commit();
        if (i < NTILES) {
            cp_wait1();          // tile i's group complete (tile i+1 outstanding)
            __syncwarp();
        }

        // ---- scan tile i-1 (no barrier vs conv below -> ptxas may interleave) ----
        if (i >= 1) {
            const float* dr = DR[(i - 1) & 1] + lane * DROW;
            float* ob = outb + (size_t)(i - 1) * TILE_T;
#pragma unroll
            for (int gg = 0; gg < 8; ++gg) {
                float4 d4 = *(const float4*)(dr + gg * 4);
                float4 sv;
                float t;
                // reset_t == spk_{t-1} (exact): mem' = fma(beta,mem,d) - 0.5*spk_prev
                t = fmaf(BETA, mem, d4.x); mem = fmaf(-THRV, spk, t);
                spk = (mem > THRV) ? 1.0f : 0.0f; sv.x = spk;
                t = fmaf(BETA, mem, d4.y); mem = fmaf(-THRV, spk, t);
                spk = (mem > THRV) ? 1.0f : 0.0f; sv.y = spk;
                t = fmaf(BETA, mem, d4.z); mem = fmaf(-THRV, spk, t);
                spk = (mem > THRV) ? 1.0f : 0.0f; sv.z = spk;
                t = fmaf(BETA, mem, d4.w); mem = fmaf(-THRV, spk, t);
                spk = (mem > THRV) ? 1.0f : 0.0f; sv.w = spk;
                *(float4*)(ob + gg * 4) = sv;
            }
        }

        // ---- conv tile i: 8-channel register strip, sliding over 20 rows ----
        if (i < NTILES) {
            const float* base = IN[i & 1] + (s * 8) * SROW + g * 4;
            ulonglong2 acc[8];
#pragma unroll
            for (int k = 0; k < 8; ++k) { acc[k].x = 0ull; acc[k].y = 0ull; }
#pragma unroll
            for (int m = 0; m < 20; ++m) {
                ulonglong2 v = *(const ulonglong2*)(base + m * SROW);
#pragma unroll
                for (int k = 0; k < 8; ++k) {
                    int j = m - k;
                    if (j >= 0 && j < KS) {
                        ffma2(acc[k].x, v.x, kp[j]);
                        ffma2(acc[k].y, v.y, kp[j]);
                    }
                }
            }
            float* dst = DR[i & 1] + (s * 8) * DROW + g * 4;
#pragma unroll
            for (int k = 0; k < 8; ++k)
                *(ulonglong2*)(dst + k * DROW) = acc[k];
        }
    }
}

extern "C" void kernel_launch(void* const* d_in, const int* in_sizes, int n_in,
                              void* d_out, int out_size) {
    const float* inp = (const float*)d_in[0];
    const float* wv  = (const float*)d_in[1];
    float* out       = (float*)d_out;

    static int smem_set = 0;
    (void)smem_set;
    cudaFuncSetAttribute(snn_lif2, cudaFuncAttributeMaxDynamicSharedMemorySize,
                         SMEM_FLOATS * 4);

    dim3 grid(CC / 128, BB);   // (4, 32) = 128 CTAs
    dim3 blk(NTHR);
    snn_lif2<<<grid, blk, SMEM_FLOATS * 4>>>(inp, wv, out);
}